// round 11
// baseline (speedup 1.0000x reference)
#include <cuda_runtime.h>
#include <cstdint>
#include <cstddef>

// ============================================================================
// RecurrentLegendreLayer via single-pass FP16 mma.sync GEMM with per-degree
// power-of-2 scaling.
//   out[b,o] = sum_{f,i} P_f(x[b,i]) * W[f,i,o] + bias[o]
// f=0 folded into bias  =>  GEMM M=16384, N=512, K=4096.
// A_f = fp16( P_f * 2^-e_f ),  W_f = fp16( W * 2^+e_f );  fp32 accumulate.
// chunk c = ib*8 + (f-1).  Stage = 4 chunks, one barrier per stage.
// R10: BM=64 x BN=128 -> 1024 tiles -> 7 waves @ 98.8% packing (vs 2 waves
//      @ 86.5%).  1 CTA/SM forced via smem. Fine-grained ldsm (R8 style).
// ============================================================================

#define NSTG    32
#define DPS     4
#define BM      64
#define BN      128
#define NTHR    512

#define APITCH  80               // 32 fp16 = 64B + pad
#define ATILE   5120             // 64 rows * APITCH
#define BPITCH  272              // 128 fp16 = 256B + pad
#define BTILE   8704             // 32 rows * BPITCH
#define SM_A    0                // 8 * ATILE = 40960
#define SM_B    40960            // 8 * BTILE = 69632
#define SMEM_TOTAL 117760        // padded >113.5KB so only 1 CTA/SM fits

__device__ uint32_t g_B[1048576];    // 4.2 MB prepared fp16 W (scaled)
__device__ float    g_bias2[512];    // bias + sum_i W[0,i,:]

// per-degree scales, f=1..8: A *= SCALE_A, W *= SCALE_W (exact powers of 2)
__device__ __constant__ float SCALE_W[8] = {1.f, 1.f, 1.f, 1.f,
                                            4.f, 32.f, 512.f, 4096.f};
__device__ __constant__ float SCALE_A[8] = {1.f, 1.f, 1.f, 1.f,
                                            0.25f, 0.03125f,
                                            1.953125e-3f, 2.44140625e-4f};

// ---------------------------------------------------------------- helpers ---
__device__ __forceinline__ uint32_t smem_u32(const void* p) {
    return (uint32_t)__cvta_generic_to_shared(p);
}
__device__ __forceinline__ void cp_async16(uint32_t dst, const void* src) {
    asm volatile("cp.async.cg.shared.global [%0], [%1], 16;"
                 :: "r"(dst), "l"(__cvta_generic_to_global(src)));
}
__device__ __forceinline__ void cp_commit() { asm volatile("cp.async.commit_group;"); }
__device__ __forceinline__ void cp_wait0() {
    asm volatile("cp.async.wait_group 0;" ::: "memory");
}
__device__ __forceinline__ void ldsm_x4(uint32_t* r, uint32_t addr) {
    asm volatile("ldmatrix.sync.aligned.m8n8.x4.shared.b16 {%0,%1,%2,%3}, [%4];"
                 : "=r"(r[0]), "=r"(r[1]), "=r"(r[2]), "=r"(r[3]) : "r"(addr));
}
__device__ __forceinline__ void ldsm_x4_t(uint32_t* r, uint32_t addr) {
    asm volatile("ldmatrix.sync.aligned.m8n8.x4.trans.shared.b16 {%0,%1,%2,%3}, [%4];"
                 : "=r"(r[0]), "=r"(r[1]), "=r"(r[2]), "=r"(r[3]) : "r"(addr));
}
__device__ __forceinline__ void mma16816f16(float* c, const uint32_t* a,
                                            uint32_t b0, uint32_t b1) {
    asm volatile(
        "mma.sync.aligned.m16n8k16.row.col.f32.f16.f16.f32 "
        "{%0,%1,%2,%3}, {%4,%5,%6,%7}, {%8,%9}, {%0,%1,%2,%3};"
        : "+f"(c[0]), "+f"(c[1]), "+f"(c[2]), "+f"(c[3])
        : "r"(a[0]), "r"(a[1]), "r"(a[2]), "r"(a[3]), "r"(b0), "r"(b1));
}
__device__ __forceinline__ uint32_t pack_h2(float a0, float a1) {
    uint32_t d;
    asm("cvt.rn.f16x2.f32 %0, %1, %2;" : "=r"(d) : "f"(a1), "f"(a0));
    return d;
}
__device__ __forceinline__ float clamp16(float v) {
    return fminf(fmaxf(v, -65000.f), 65000.f);
}

// ---------------------------------------------------------------- prepass ---
// g_B word index = ((c*32 + k)*512 + n) / 2,  c = ib*8 + (f-1).  Vectorized.
__global__ void leg_prep_kernel(const float* __restrict__ w) {
    uint32_t g  = blockIdx.x * 256 + threadIdx.x;      // 262144 groups
    uint32_t n8 = g & 63;                              // n = n8*8
    uint32_t q  = g >> 6;                              // 0..4095
    uint32_t k  = q & 31;
    uint32_t c  = q >> 5;                              // 0..127
    uint32_t f  = (c & 7) + 1;                         // 1..8
    uint32_t ib = c >> 3;
    const float sw = SCALE_W[f - 1];
    const float4* src = (const float4*)(w
        + ((size_t)(f * 512 + ib * 32 + k)) * 512 + n8 * 8);
    float4 v0 = src[0], v1 = src[1];
    uint4 o;
    o.x = pack_h2(v0.x * sw, v0.y * sw);
    o.y = pack_h2(v0.z * sw, v0.w * sw);
    o.z = pack_h2(v1.x * sw, v1.y * sw);
    o.w = pack_h2(v1.z * sw, v1.w * sw);
    *(uint4*)(g_B + (size_t)g * 4) = o;
}

__global__ void leg_bias_kernel(const float* __restrict__ w,
                                const float* __restrict__ bias) {
    int o = blockIdx.x * 128 + threadIdx.x;
    float s = bias[o];
    #pragma unroll 8
    for (int i = 0; i < 512; ++i) s += w[(size_t)i * 512 + o];
    g_bias2[o] = s;
}

// ------------------------------------------------------------ main kernel ---
__global__ __launch_bounds__(NTHR, 1)
void leg_mma_kernel(const float* __restrict__ x,
                    float* __restrict__ out)
{
    extern __shared__ char sm[];
    const uint32_t sb = smem_u32(sm);
    const int tid    = threadIdx.x;
    const int lane   = tid & 31;
    const int wid    = tid >> 5;
    const int warp_m = wid & 1;          // 2 M-warps (32 rows each)
    const int warp_n = wid >> 1;         // 8 N-warps (16 cols each)
    const int bn = blockIdx.x * BN;
    const int bm = blockIdx.y * BM;

    float acc[2][2][4];
    #pragma unroll
    for (int a = 0; a < 2; ++a)
        #pragma unroll
        for (int b = 0; b < 2; ++b)
            #pragma unroll
            for (int d = 0; d < 4; ++d) acc[a][b][d] = 0.0f;

    // Legendre state: thread owns row am = tid/8, i-range ai0..ai0+4
    const int am  = tid >> 3;            // 0..63
    const int ai0 = (tid & 7) * 4;
    float xv[4], pm1[4], pm2[4];

    const uint32_t aRow = (uint32_t)(warp_m * 32 + (lane & 15)) * APITCH
                        + (uint32_t)(lane >> 4) * 16;
    const uint32_t bRow = (uint32_t)(lane & 15) * BPITCH
                        + ((uint32_t)(warp_n * 16) + (uint32_t)(lane >> 4) * 8) * 2;

    // ---- B stage loader: 4 chunks = 32KB (4 x 16B per thread)
    auto issue_load = [&](int t) {
        const int buf = t & 1;
        #pragma unroll
        for (int j = 0; j < 4; ++j) {
            int seg = tid + j * NTHR;      // 0..2047
            int d   = seg >> 9;            // 0..3
            int r   = seg & 511;
            int k   = r >> 4;
            int n16 = r & 15;
            int c   = t * DPS + d;
            uint32_t dst = sb + SM_B + (uint32_t)(buf * DPS + d) * BTILE
                         + (uint32_t)k * BPITCH + (uint32_t)n16 * 16;
            const char* src = (const char*)g_B
                + (((size_t)c * 32 + k) * 512 + bn + n16 * 8) * 2;
            cp_async16(dst, src);
        }
        cp_commit();
    };

    issue_load(0);

    for (int t = 0; t < NSTG; ++t) {
        const int buf = t & 1;

        // ---- compute A for the 4 chunks of stage t (before the barrier).
        // Buf (t&1) last read by MMA(t-2), retired by barrier(t-1).
        #pragma unroll
        for (int d = 0; d < DPS; ++d) {
            const int c  = t * DPS + d;
            const int f  = (c & 7) + 1;    // 1..8
            float p[4];
            if (f == 1) {
                const int ib = c >> 3;
                float4 v0 = *(const float4*)(x + (size_t)(bm + am) * 512
                                             + ib * 32 + ai0);
                xv[0]=v0.x; xv[1]=v0.y; xv[2]=v0.z; xv[3]=v0.w;
                #pragma unroll
                for (int j = 0; j < 4; ++j) { p[j] = xv[j]; pm2[j] = 1.0f; pm1[j] = xv[j]; }
            } else {
                const float fv = (float)f;
                const float c1 = (2.0f * fv - 1.0f) / fv;
                const float c2 = (fv - 1.0f) / fv;
                #pragma unroll
                for (int j = 0; j < 4; ++j) {
                    float pn = c1 * xv[j] * pm1[j] - c2 * pm2[j];
                    pm2[j] = pm1[j]; pm1[j] = pn; p[j] = pn;
                }
            }
            const float sa = SCALE_A[f - 1];
            uint32_t w0 = pack_h2(clamp16(p[0] * sa), clamp16(p[1] * sa));
            uint32_t w1 = pack_h2(clamp16(p[2] * sa), clamp16(p[3] * sa));
            uint32_t aaddr = sb + SM_A + (uint32_t)(buf * DPS + d) * ATILE
                           + (uint32_t)am * APITCH + (uint32_t)ai0 * 2;
            asm volatile("st.shared.v2.b32 [%0], {%1,%2};"
                         :: "r"(aaddr), "r"(w0), "r"(w1));
        }

        cp_wait0();
        __syncthreads();                 // publish A(t)+B(t); retire MMA(t-1)
        if (t + 1 < NSTG) issue_load(t + 1);

        // ---- single-pass MMA over the 4 chunks (fine-grained ldsm, R8 style)
        #pragma unroll
        for (int d = 0; d < DPS; ++d) {
            const uint32_t aT = sb + SM_A + (uint32_t)(buf * DPS + d) * ATILE + aRow;
            const uint32_t bT = sb + SM_B + (uint32_t)(buf * DPS + d) * BTILE + bRow;

            #pragma unroll
            for (int k16 = 0; k16 < 2; ++k16) {
                const uint32_t aOff = (uint32_t)k16 * 32;
                const uint32_t bOff = (uint32_t)(k16 * 16) * BPITCH;
                uint32_t ah[2][4], bb[4];

                ldsm_x4(ah[0], aT + aOff);
                ldsm_x4(ah[1], aT + aOff + 16 * APITCH);
                ldsm_x4_t(bb, bT + bOff);

                #pragma unroll
                for (int mf = 0; mf < 2; ++mf) {
                    mma16816f16(acc[mf][0], ah[mf], bb[0], bb[1]);
                    mma16816f16(acc[mf][1], ah[mf], bb[2], bb[3]);
                }
            }
        }
    }

    // ---- epilogue: bias add + store
    const int r0 = bm + warp_m * 32 + (lane >> 2);
    const int c0 = bn + warp_n * 16 + (lane & 3) * 2;
    #pragma unroll
    for (int mf = 0; mf < 2; ++mf) {
        #pragma unroll
        for (int nf = 0; nf < 2; ++nf) {
            const int row = r0 + mf * 16;
            const int col = c0 + nf * 8;
            const float2 bv = *(const float2*)(g_bias2 + col);
            float2 v0, v1;
            v0.x = acc[mf][nf][0] + bv.x;  v0.y = acc[mf][nf][1] + bv.y;
            v1.x = acc[mf][nf][2] + bv.x;  v1.y = acc[mf][nf][3] + bv.y;
            *(float2*)(out + (size_t)row * 512 + col)       = v0;
            *(float2*)(out + (size_t)(row + 8) * 512 + col) = v1;
        }
    }
}

// ------------------------------------------------------------------ launch --
extern "C" void kernel_launch(void* const* d_in, const int* in_sizes, int n_in,
                              void* d_out, int out_size)
{
    const float* x    = (const float*)d_in[0];
    const float* w    = (const float*)d_in[1];
    const float* bias = (const float*)d_in[2];
    float* out        = (float*)d_out;

    const int B = in_sizes[0] / 512;             // 16384

    cudaFuncSetAttribute(leg_mma_kernel,
                         cudaFuncAttributeMaxDynamicSharedMemorySize,
                         SMEM_TOTAL);

    leg_prep_kernel<<<1024, 256>>>(w);           // 262144 groups x 4 words
    leg_bias_kernel<<<4, 128>>>(w, bias);

    dim3 grid(512 / BN, B / BM);                 // (4, 256) = 1024 CTAs
    leg_mma_kernel<<<grid, NTHR, SMEM_TOTAL>>>(x, out);
}

// round 12
// speedup vs baseline: 1.5379x; 1.5379x over previous
#include <cuda_runtime.h>
#include <cstdint>
#include <cstddef>

// ============================================================================
// RecurrentLegendreLayer via single-pass FP16 mma.sync GEMM with per-degree
// power-of-2 scaling.
//   out[b,o] = sum_{f,i} P_f(x[b,i]) * W[f,i,o] + bias[o]
// f=0 folded into bias  =>  GEMM M=16384, N=512, K=4096.
// A_f = fp16( P_f * 2^-e_f ),  W_f = fp16( W * 2^+e_f );  fp32 accumulate.
// chunk c = ib*8 + (f-1).  Stage = 4 chunks, one barrier per stage.
// R11: R8 tile shape (BM=128, BN=256, 512 thr).  A-compute for stage t+1 is
//      interleaved with the MMA span of stage t (mma non-volatile so ptxas
//      can fill the idle issue slots); A(0) peeled before the loop.
// ============================================================================

#define NSTG    32
#define DPS     4
#define BM      128
#define BN      256
#define NTHR    512

#define APITCH  80
#define ATILE   10240
#define BPITCH  528
#define BTILE   16896
#define SM_A    0
#define SM_B    81920            // 8 * ATILE
#define SMEM_TOTAL 217088        // SM_B + 8 * BTILE

__device__ uint32_t g_B[1048576];    // 4.2 MB prepared fp16 W (scaled)
__device__ float    g_bias2[512];    // bias + sum_i W[0,i,:]

// per-degree scales, f=1..8: A *= SCALE_A, W *= SCALE_W (exact powers of 2)
__device__ __constant__ float SCALE_W[8] = {1.f, 1.f, 1.f, 1.f,
                                            4.f, 32.f, 512.f, 4096.f};
__device__ __constant__ float SCALE_A[8] = {1.f, 1.f, 1.f, 1.f,
                                            0.25f, 0.03125f,
                                            1.953125e-3f, 2.44140625e-4f};

// ---------------------------------------------------------------- helpers ---
__device__ __forceinline__ uint32_t smem_u32(const void* p) {
    return (uint32_t)__cvta_generic_to_shared(p);
}
__device__ __forceinline__ void cp_async16(uint32_t dst, const void* src) {
    asm volatile("cp.async.cg.shared.global [%0], [%1], 16;"
                 :: "r"(dst), "l"(__cvta_generic_to_global(src)));
}
__device__ __forceinline__ void cp_commit() { asm volatile("cp.async.commit_group;"); }
__device__ __forceinline__ void cp_wait0() {
    asm volatile("cp.async.wait_group 0;" ::: "memory");
}
__device__ __forceinline__ void ldsm_x4(uint32_t* r, uint32_t addr) {
    asm volatile("ldmatrix.sync.aligned.m8n8.x4.shared.b16 {%0,%1,%2,%3}, [%4];"
                 : "=r"(r[0]), "=r"(r[1]), "=r"(r[2]), "=r"(r[3]) : "r"(addr));
}
__device__ __forceinline__ void ldsm_x4_t(uint32_t* r, uint32_t addr) {
    asm volatile("ldmatrix.sync.aligned.m8n8.x4.trans.shared.b16 {%0,%1,%2,%3}, [%4];"
                 : "=r"(r[0]), "=r"(r[1]), "=r"(r[2]), "=r"(r[3]) : "r"(addr));
}
// NOTE: non-volatile on purpose — pure register computation, outputs consumed;
// data deps pin it below its ldmatrix, and ptxas may interleave independent
// FMA work (next stage's Legendre recurrence) into the HMMA issue bubbles.
__device__ __forceinline__ void mma16816f16(float* c, const uint32_t* a,
                                            uint32_t b0, uint32_t b1) {
    asm("mma.sync.aligned.m16n8k16.row.col.f32.f16.f16.f32 "
        "{%0,%1,%2,%3}, {%4,%5,%6,%7}, {%8,%9}, {%0,%1,%2,%3};"
        : "+f"(c[0]), "+f"(c[1]), "+f"(c[2]), "+f"(c[3])
        : "r"(a[0]), "r"(a[1]), "r"(a[2]), "r"(a[3]), "r"(b0), "r"(b1));
}
__device__ __forceinline__ uint32_t pack_h2(float a0, float a1) {
    uint32_t d;
    asm("cvt.rn.f16x2.f32 %0, %1, %2;" : "=r"(d) : "f"(a1), "f"(a0));
    return d;
}
__device__ __forceinline__ float clamp16(float v) {
    return fminf(fmaxf(v, -65000.f), 65000.f);
}

// ---------------------------------------------------------------- prepass ---
// g_B word index = ((c*32 + k)*512 + n) / 2,  c = ib*8 + (f-1).  Vectorized.
__global__ void leg_prep_kernel(const float* __restrict__ w) {
    uint32_t g  = blockIdx.x * 256 + threadIdx.x;      // 262144 groups
    uint32_t n8 = g & 63;
    uint32_t q  = g >> 6;
    uint32_t k  = q & 31;
    uint32_t c  = q >> 5;
    uint32_t f  = (c & 7) + 1;
    uint32_t ib = c >> 3;
    const float sw = SCALE_W[f - 1];
    const float4* src = (const float4*)(w
        + ((size_t)(f * 512 + ib * 32 + k)) * 512 + n8 * 8);
    float4 v0 = src[0], v1 = src[1];
    uint4 o;
    o.x = pack_h2(v0.x * sw, v0.y * sw);
    o.y = pack_h2(v0.z * sw, v0.w * sw);
    o.z = pack_h2(v1.x * sw, v1.y * sw);
    o.w = pack_h2(v1.z * sw, v1.w * sw);
    *(uint4*)(g_B + (size_t)g * 4) = o;
}

__global__ void leg_bias_kernel(const float* __restrict__ w,
                                const float* __restrict__ bias) {
    int o = blockIdx.x * 128 + threadIdx.x;
    float s = bias[o];
    #pragma unroll 8
    for (int i = 0; i < 512; ++i) s += w[(size_t)i * 512 + o];
    g_bias2[o] = s;
}

// ------------------------------------------------------------ main kernel ---
__global__ __launch_bounds__(NTHR, 1)
void leg_mma_kernel(const float* __restrict__ x,
                    float* __restrict__ out)
{
    extern __shared__ char sm[];
    const uint32_t sb = smem_u32(sm);
    const int tid    = threadIdx.x;
    const int lane   = tid & 31;
    const int wid    = tid >> 5;
    const int warp_m = wid & 3;
    const int warp_n = wid >> 2;
    const int bn = blockIdx.x * BN;
    const int bm = blockIdx.y * BM;

    float acc[2][8][4];
    #pragma unroll
    for (int a = 0; a < 2; ++a)
        #pragma unroll
        for (int b = 0; b < 8; ++b)
            #pragma unroll
            for (int d = 0; d < 4; ++d) acc[a][b][d] = 0.0f;

    const int am  = tid >> 2;
    const int ai0 = (tid & 3) * 8;
    float xv[8], pm1[8], pm2[8];

    const uint32_t aRow = (uint32_t)(warp_m * 32 + (lane & 15)) * APITCH
                        + (uint32_t)(lane >> 4) * 16;
    const uint32_t bRow = (uint32_t)(lane & 15) * BPITCH
                        + ((uint32_t)(warp_n * 64) + (uint32_t)(lane >> 4) * 8) * 2;

    // ---- A compute for one chunk c into buffer slot (bufsel, d)
    auto computeA = [&](int c, int bufsel, int d) {
        const int f = (c & 7) + 1;         // 1..8
        float p[8];
        if (f == 1) {
            const int ib = c >> 3;
            const float4* xp = (const float4*)(x + (size_t)(bm + am) * 512
                                               + ib * 32 + ai0);
            float4 v0 = xp[0], v1 = xp[1];
            xv[0]=v0.x; xv[1]=v0.y; xv[2]=v0.z; xv[3]=v0.w;
            xv[4]=v1.x; xv[5]=v1.y; xv[6]=v1.z; xv[7]=v1.w;
            #pragma unroll
            for (int j = 0; j < 8; ++j) { p[j] = xv[j]; pm2[j] = 1.0f; pm1[j] = xv[j]; }
        } else {
            const float fv = (float)f;
            const float c1 = (2.0f * fv - 1.0f) / fv;
            const float c2 = (fv - 1.0f) / fv;
            #pragma unroll
            for (int j = 0; j < 8; ++j) {
                float pn = c1 * xv[j] * pm1[j] - c2 * pm2[j];
                pm2[j] = pm1[j]; pm1[j] = pn; p[j] = pn;
            }
        }
        const float sa = SCALE_A[f - 1];
        uint32_t wds[4];
        #pragma unroll
        for (int j2 = 0; j2 < 4; ++j2) {
            wds[j2] = pack_h2(clamp16(p[2*j2]   * sa),
                              clamp16(p[2*j2+1] * sa));
        }
        uint32_t aaddr = sb + SM_A + (uint32_t)(bufsel * DPS + d) * ATILE
                       + (uint32_t)am * APITCH + (uint32_t)ai0 * 2;
        asm volatile("st.shared.v4.b32 [%0], {%1,%2,%3,%4};"
                     :: "r"(aaddr), "r"(wds[0]), "r"(wds[1]), "r"(wds[2]), "r"(wds[3]));
    };

    // ---- B stage loader: 4 chunks = 64KB (8 x 16B per thread)
    auto issue_load = [&](int t) {
        const int buf = t & 1;
        #pragma unroll
        for (int j = 0; j < 8; ++j) {
            int seg = tid + j * NTHR;
            int d   = seg >> 10;
            int r   = seg & 1023;
            int k   = r >> 5;
            int n16 = r & 31;
            int c   = t * DPS + d;
            uint32_t dst = sb + SM_B + (uint32_t)(buf * DPS + d) * BTILE
                         + (uint32_t)k * BPITCH + (uint32_t)n16 * 16;
            const char* src = (const char*)g_B
                + (((size_t)c * 32 + k) * 512 + bn + n16 * 8) * 2;
            cp_async16(dst, src);
        }
        cp_commit();
    };

    issue_load(0);
    // peel: A for stage 0 into buf 0
    #pragma unroll
    for (int d = 0; d < DPS; ++d) computeA(d, 0, d);

    for (int t = 0; t < NSTG; ++t) {
        const int buf  = t & 1;
        const int nbuf = buf ^ 1;

        cp_wait0();
        __syncthreads();                 // publish A(t)+B(t); retire MMA(t-1)
        if (t + 1 < NSTG) issue_load(t + 1);

        // ---- MMA over the 4 chunks of stage t, interleaved with A(t+1).
        // A(t+1) writes buf (t+1)&1, whose last reader MMA(t-1) retired at
        // the barrier above.  mma is non-volatile so the A-compute FMA chain
        // can fill HMMA issue bubbles.
        #pragma unroll
        for (int d = 0; d < DPS; ++d) {
            const uint32_t aT = sb + SM_A + (uint32_t)(buf * DPS + d) * ATILE + aRow;
            const uint32_t bT = sb + SM_B + (uint32_t)(buf * DPS + d) * BTILE + bRow;

            #pragma unroll
            for (int k16 = 0; k16 < 2; ++k16) {
                const uint32_t aOff = (uint32_t)k16 * 32;
                const uint32_t bOff = (uint32_t)(k16 * 16) * BPITCH;
                uint32_t ah[2][4], bb[4][4];

                ldsm_x4(ah[0], aT + aOff);
                ldsm_x4(ah[1], aT + aOff + 16 * APITCH);
                #pragma unroll
                for (int nf = 0; nf < 4; ++nf) ldsm_x4_t(bb[nf], bT + bOff + nf * 32);

                #pragma unroll
                for (int mf = 0; mf < 2; ++mf)
                    #pragma unroll
                    for (int nf = 0; nf < 4; ++nf) {
                        mma16816f16(acc[mf][nf * 2 + 0], ah[mf], bb[nf][0], bb[nf][1]);
                        mma16816f16(acc[mf][nf * 2 + 1], ah[mf], bb[nf][2], bb[nf][3]);
                    }
            }
            // interleave: next stage's A for chunk d (recurrence chain spread
            // across the 4 MMA blocks)
            if (t + 1 < NSTG) computeA((t + 1) * DPS + d, nbuf, d);
        }
    }

    // ---- epilogue: bias add + store
    const int r0 = bm + warp_m * 32 + (lane >> 2);
    const int c0 = bn + warp_n * 64 + (lane & 3) * 2;
    #pragma unroll
    for (int mf = 0; mf < 2; ++mf) {
        #pragma unroll
        for (int nf = 0; nf < 8; ++nf) {
            const int row = r0 + mf * 16;
            const int col = c0 + nf * 8;
            const float2 bv = *(const float2*)(g_bias2 + col);
            float2 v0, v1;
            v0.x = acc[mf][nf][0] + bv.x;  v0.y = acc[mf][nf][1] + bv.y;
            v1.x = acc[mf][nf][2] + bv.x;  v1.y = acc[mf][nf][3] + bv.y;
            *(float2*)(out + (size_t)row * 512 + col)       = v0;
            *(float2*)(out + (size_t)(row + 8) * 512 + col) = v1;
        }
    }
}

// ------------------------------------------------------------------ launch --
extern "C" void kernel_launch(void* const* d_in, const int* in_sizes, int n_in,
                              void* d_out, int out_size)
{
    const float* x    = (const float*)d_in[0];
    const float* w    = (const float*)d_in[1];
    const float* bias = (const float*)d_in[2];
    float* out        = (float*)d_out;

    const int B = in_sizes[0] / 512;             // 16384

    cudaFuncSetAttribute(leg_mma_kernel,
                         cudaFuncAttributeMaxDynamicSharedMemorySize,
                         SMEM_TOTAL);

    leg_prep_kernel<<<1024, 256>>>(w);           // 262144 groups x 4 words
    leg_bias_kernel<<<4, 128>>>(w, bias);

    dim3 grid(512 / BN, B / BM);                 // (2, 128)
    leg_mma_kernel<<<grid, NTHR, SMEM_TOTAL>>>(x, out);
}

// round 13
// speedup vs baseline: 1.7607x; 1.1449x over previous
#include <cuda_runtime.h>
#include <cstdint>
#include <cstddef>

// ============================================================================
// RecurrentLegendreLayer via single-pass FP16 mma.sync GEMM with per-degree
// power-of-2 scaling.
//   out[b,o] = sum_{f,i} P_f(x[b,i]) * W[f,i,o] + bias[o]
// f=0 folded into bias  =>  GEMM M=16384, N=512, K=4096.
// A_f = fp16( P_f * 2^-e_f ),  W_f = fp16( W * 2^+e_f );  fp32 accumulate.
// chunk c = ib*8 + (f-1).  Stage = 4 chunks, one barrier per stage.
// R12: main kernel byte-identical to R8 (the 282.7us champion).  Aux kernels
//      fixed: bias-fold now a parallel block-per-column reduction (~18us ->
//      ~2us); prep kernel 2 groups/thread for MLP 4.
// ============================================================================

#define NSTG    32
#define DPS     4
#define BM      128
#define BN      256
#define NTHR    512

#define APITCH  80
#define ATILE   10240
#define BPITCH  528
#define BTILE   16896
#define SM_A    0
#define SM_B    81920            // 8 * ATILE
#define SMEM_TOTAL 217088        // SM_B + 8 * BTILE

__device__ uint32_t g_B[1048576];    // 4.2 MB prepared fp16 W (scaled)
__device__ float    g_bias2[512];    // bias + sum_i W[0,i,:]

// per-degree scales, f=1..8: A *= SCALE_A, W *= SCALE_W (exact powers of 2)
__device__ __constant__ float SCALE_W[8] = {1.f, 1.f, 1.f, 1.f,
                                            4.f, 32.f, 512.f, 4096.f};
__device__ __constant__ float SCALE_A[8] = {1.f, 1.f, 1.f, 1.f,
                                            0.25f, 0.03125f,
                                            1.953125e-3f, 2.44140625e-4f};

// ---------------------------------------------------------------- helpers ---
__device__ __forceinline__ uint32_t smem_u32(const void* p) {
    return (uint32_t)__cvta_generic_to_shared(p);
}
__device__ __forceinline__ void cp_async16(uint32_t dst, const void* src) {
    asm volatile("cp.async.cg.shared.global [%0], [%1], 16;"
                 :: "r"(dst), "l"(__cvta_generic_to_global(src)));
}
__device__ __forceinline__ void cp_commit() { asm volatile("cp.async.commit_group;"); }
__device__ __forceinline__ void cp_wait0() {
    asm volatile("cp.async.wait_group 0;" ::: "memory");
}
__device__ __forceinline__ void ldsm_x4(uint32_t* r, uint32_t addr) {
    asm volatile("ldmatrix.sync.aligned.m8n8.x4.shared.b16 {%0,%1,%2,%3}, [%4];"
                 : "=r"(r[0]), "=r"(r[1]), "=r"(r[2]), "=r"(r[3]) : "r"(addr));
}
__device__ __forceinline__ void ldsm_x4_t(uint32_t* r, uint32_t addr) {
    asm volatile("ldmatrix.sync.aligned.m8n8.x4.trans.shared.b16 {%0,%1,%2,%3}, [%4];"
                 : "=r"(r[0]), "=r"(r[1]), "=r"(r[2]), "=r"(r[3]) : "r"(addr));
}
__device__ __forceinline__ void mma16816f16(float* c, const uint32_t* a,
                                            uint32_t b0, uint32_t b1) {
    asm volatile(
        "mma.sync.aligned.m16n8k16.row.col.f32.f16.f16.f32 "
        "{%0,%1,%2,%3}, {%4,%5,%6,%7}, {%8,%9}, {%0,%1,%2,%3};"
        : "+f"(c[0]), "+f"(c[1]), "+f"(c[2]), "+f"(c[3])
        : "r"(a[0]), "r"(a[1]), "r"(a[2]), "r"(a[3]), "r"(b0), "r"(b1));
}
__device__ __forceinline__ uint32_t pack_h2(float a0, float a1) {
    uint32_t d;
    asm("cvt.rn.f16x2.f32 %0, %1, %2;" : "=r"(d) : "f"(a1), "f"(a0));
    return d;
}
__device__ __forceinline__ float clamp16(float v) {
    return fminf(fmaxf(v, -65000.f), 65000.f);
}

// ---------------------------------------------------------------- prepass ---
// g_B word index = ((c*32 + k)*512 + n) / 2,  c = ib*8 + (f-1).
// 2 groups (16 n-values) per thread -> 4 independent float4 loads (MLP 4).
__global__ void leg_prep_kernel(const float* __restrict__ w) {
    uint32_t g0 = (blockIdx.x * 256 + threadIdx.x) * 2;    // 262144 groups total
    #pragma unroll
    for (int gg = 0; gg < 2; ++gg) {
        uint32_t g  = g0 + gg;
        uint32_t n8 = g & 63;
        uint32_t q  = g >> 6;
        uint32_t k  = q & 31;
        uint32_t c  = q >> 5;
        uint32_t f  = (c & 7) + 1;
        uint32_t ib = c >> 3;
        const float sw = SCALE_W[f - 1];
        const float4* src = (const float4*)(w
            + ((size_t)(f * 512 + ib * 32 + k)) * 512 + n8 * 8);
        float4 v0 = src[0], v1 = src[1];
        uint4 o;
        o.x = pack_h2(v0.x * sw, v0.y * sw);
        o.y = pack_h2(v0.z * sw, v0.w * sw);
        o.z = pack_h2(v1.x * sw, v1.y * sw);
        o.w = pack_h2(v1.z * sw, v1.w * sw);
        *(uint4*)(g_B + (size_t)g * 4) = o;
    }
}

// bias2[o] = bias[o] + sum_i W[0,i,o].  Block per column, 128-thread
// tree reduction; adjacent blocks hit the same 128B lines (L2 reuse).
__global__ void leg_bias_kernel(const float* __restrict__ w,
                                const float* __restrict__ bias) {
    __shared__ float red[128];
    const int o   = blockIdx.x;           // 512 blocks
    const int tid = threadIdx.x;          // 128 threads
    float s = 0.0f;
    #pragma unroll
    for (int j = 0; j < 4; ++j)
        s += w[(size_t)(tid + j * 128) * 512 + o];
    red[tid] = s;
    __syncthreads();
    #pragma unroll
    for (int off = 64; off > 0; off >>= 1) {
        if (tid < off) red[tid] += red[tid + off];
        __syncthreads();
    }
    if (tid == 0) g_bias2[o] = red[0] + bias[o];
}

// ------------------------------------------------------------ main kernel ---
// Byte-identical to the R8 champion (282.7us).
__global__ __launch_bounds__(NTHR, 1)
void leg_mma_kernel(const float* __restrict__ x,
                    float* __restrict__ out)
{
    extern __shared__ char sm[];
    const uint32_t sb = smem_u32(sm);
    const int tid    = threadIdx.x;
    const int lane   = tid & 31;
    const int wid    = tid >> 5;
    const int warp_m = wid & 3;
    const int warp_n = wid >> 2;
    const int bn = blockIdx.x * BN;
    const int bm = blockIdx.y * BM;

    float acc[2][8][4];
    #pragma unroll
    for (int a = 0; a < 2; ++a)
        #pragma unroll
        for (int b = 0; b < 8; ++b)
            #pragma unroll
            for (int d = 0; d < 4; ++d) acc[a][b][d] = 0.0f;

    const int am  = tid >> 2;
    const int ai0 = (tid & 3) * 8;
    float xv[8], pm1[8], pm2[8];

    const uint32_t aRow = (uint32_t)(warp_m * 32 + (lane & 15)) * APITCH
                        + (uint32_t)(lane >> 4) * 16;
    const uint32_t bRow = (uint32_t)(lane & 15) * BPITCH
                        + ((uint32_t)(warp_n * 64) + (uint32_t)(lane >> 4) * 8) * 2;

    // ---- B stage loader: 4 chunks = 64KB (8 x 16B per thread)
    auto issue_load = [&](int t) {
        const int buf = t & 1;
        #pragma unroll
        for (int j = 0; j < 8; ++j) {
            int seg = tid + j * NTHR;      // 0..4095
            int d   = seg >> 10;           // 0..3
            int r   = seg & 1023;
            int k   = r >> 5;
            int n16 = r & 31;
            int c   = t * DPS + d;
            uint32_t dst = sb + SM_B + (uint32_t)(buf * DPS + d) * BTILE
                         + (uint32_t)k * BPITCH + (uint32_t)n16 * 16;
            const char* src = (const char*)g_B
                + (((size_t)c * 32 + k) * 512 + bn + n16 * 8) * 2;
            cp_async16(dst, src);
        }
        cp_commit();
    };

    issue_load(0);

    for (int t = 0; t < NSTG; ++t) {
        const int buf = t & 1;

        // ---- compute A for the 4 chunks of stage t (before the barrier).
        #pragma unroll
        for (int d = 0; d < DPS; ++d) {
            const int c  = t * DPS + d;
            const int f  = (c & 7) + 1;    // 1..8
            float p[8];
            if (f == 1) {
                const int ib = c >> 3;
                const float4* xp = (const float4*)(x + (size_t)(bm + am) * 512
                                                   + ib * 32 + ai0);
                float4 v0 = xp[0], v1 = xp[1];
                xv[0]=v0.x; xv[1]=v0.y; xv[2]=v0.z; xv[3]=v0.w;
                xv[4]=v1.x; xv[5]=v1.y; xv[6]=v1.z; xv[7]=v1.w;
                #pragma unroll
                for (int j = 0; j < 8; ++j) { p[j] = xv[j]; pm2[j] = 1.0f; pm1[j] = xv[j]; }
            } else {
                const float fv = (float)f;
                const float c1 = (2.0f * fv - 1.0f) / fv;
                const float c2 = (fv - 1.0f) / fv;
                #pragma unroll
                for (int j = 0; j < 8; ++j) {
                    float pn = c1 * xv[j] * pm1[j] - c2 * pm2[j];
                    pm2[j] = pm1[j]; pm1[j] = pn; p[j] = pn;
                }
            }
            const float sa = SCALE_A[f - 1];
            uint32_t wds[4];
            #pragma unroll
            for (int j2 = 0; j2 < 4; ++j2) {
                wds[j2] = pack_h2(clamp16(p[2*j2]   * sa),
                                  clamp16(p[2*j2+1] * sa));
            }
            uint32_t aaddr = sb + SM_A + (uint32_t)(buf * DPS + d) * ATILE
                           + (uint32_t)am * APITCH + (uint32_t)ai0 * 2;
            asm volatile("st.shared.v4.b32 [%0], {%1,%2,%3,%4};"
                         :: "r"(aaddr), "r"(wds[0]), "r"(wds[1]), "r"(wds[2]), "r"(wds[3]));
        }

        cp_wait0();
        __syncthreads();                 // publish A(t)+B(t); retire MMA(t-1)
        if (t + 1 < NSTG) issue_load(t + 1);

        // ---- single-pass MMA over the 4 chunks (fine-grained ldsm)
        #pragma unroll
        for (int d = 0; d < DPS; ++d) {
            const uint32_t aT = sb + SM_A + (uint32_t)(buf * DPS + d) * ATILE + aRow;
            const uint32_t bT = sb + SM_B + (uint32_t)(buf * DPS + d) * BTILE + bRow;

            #pragma unroll
            for (int k16 = 0; k16 < 2; ++k16) {
                const uint32_t aOff = (uint32_t)k16 * 32;
                const uint32_t bOff = (uint32_t)(k16 * 16) * BPITCH;
                uint32_t ah[2][4], bb[4][4];

                ldsm_x4(ah[0], aT + aOff);
                ldsm_x4(ah[1], aT + aOff + 16 * APITCH);
                #pragma unroll
                for (int nf = 0; nf < 4; ++nf) ldsm_x4_t(bb[nf], bT + bOff + nf * 32);

                #pragma unroll
                for (int mf = 0; mf < 2; ++mf)
                    #pragma unroll
                    for (int nf = 0; nf < 4; ++nf) {
                        mma16816f16(acc[mf][nf * 2 + 0], ah[mf], bb[nf][0], bb[nf][1]);
                        mma16816f16(acc[mf][nf * 2 + 1], ah[mf], bb[nf][2], bb[nf][3]);
                    }
            }
        }
    }

    // ---- epilogue: bias add + store
    const int r0 = bm + warp_m * 32 + (lane >> 2);
    const int c0 = bn + warp_n * 64 + (lane & 3) * 2;
    #pragma unroll
    for (int mf = 0; mf < 2; ++mf) {
        #pragma unroll
        for (int nf = 0; nf < 8; ++nf) {
            const int row = r0 + mf * 16;
            const int col = c0 + nf * 8;
            const float2 bv = *(const float2*)(g_bias2 + col);
            float2 v0, v1;
            v0.x = acc[mf][nf][0] + bv.x;  v0.y = acc[mf][nf][1] + bv.y;
            v1.x = acc[mf][nf][2] + bv.x;  v1.y = acc[mf][nf][3] + bv.y;
            *(float2*)(out + (size_t)row * 512 + col)       = v0;
            *(float2*)(out + (size_t)(row + 8) * 512 + col) = v1;
        }
    }
}

// ------------------------------------------------------------------ launch --
extern "C" void kernel_launch(void* const* d_in, const int* in_sizes, int n_in,
                              void* d_out, int out_size)
{
    const float* x    = (const float*)d_in[0];
    const float* w    = (const float*)d_in[1];
    const float* bias = (const float*)d_in[2];
    float* out        = (float*)d_out;

    const int B = in_sizes[0] / 512;             // 16384

    cudaFuncSetAttribute(leg_mma_kernel,
                         cudaFuncAttributeMaxDynamicSharedMemorySize,
                         SMEM_TOTAL);

    leg_prep_kernel<<<512, 256>>>(w);            // 262144 groups, 2 per thread
    leg_bias_kernel<<<512, 128>>>(w, bias);      // block-per-column reduction

    dim3 grid(512 / BN, B / BM);                 // (2, 128)
    leg_mma_kernel<<<grid, NTHR, SMEM_TOTAL>>>(x, out);
}

// round 14
// speedup vs baseline: 1.9356x; 1.0993x over previous
#include <cuda_runtime.h>
#include <cstdint>
#include <cstddef>

// ============================================================================
// RecurrentLegendreLayer via single-pass FP16 mma.sync GEMM with per-degree
// power-of-2 scaling.
//   out[b,o] = sum_{f,i} P_f(x[b,i]) * W[f,i,o] + bias[o]
// f=0 folded into bias  =>  GEMM M=16384, N=512, K=4096.
// A_f = fp16( P_f * 2^-e_f ),  W_f = fp16( W * 2^+e_f );  fp32 accumulate.
// chunk c = ib*8 + (f-1).  Stage = 4 chunks, one barrier per stage.
// R13: main loop frozen at the R8/R12 champion shape.  A-region: recurrence
//      carried in SCALED form q_f = P_f*2^-e via constant tables C1A/C2A
//      (removes 2 runtime fdivs + 1 mul per chunk; bit-identical numerics),
//      clamp only for f>=5.
// ============================================================================

#define NSTG    32
#define DPS     4
#define BM      128
#define BN      256
#define NTHR    512

#define APITCH  80
#define ATILE   10240
#define BPITCH  528
#define BTILE   16896
#define SM_A    0
#define SM_B    81920            // 8 * ATILE
#define SMEM_TOTAL 217088        // SM_B + 8 * BTILE

__device__ uint32_t g_B[1048576];    // 4.2 MB prepared fp16 W (scaled)
__device__ float    g_bias2[512];    // bias + sum_i W[0,i,:]

// W prep scales (powers of 2): W_f *= 2^{+e_f}
__device__ __constant__ float SCALE_W[8] = {1.f, 1.f, 1.f, 1.f,
                                            4.f, 32.f, 512.f, 4096.f};
// Scaled-recurrence constants for q_f = P_f * 2^{-e_f}, f = 2..8:
//   q_f = C1A[f-2] * x * q_{f-1} - C2A[f-2] * q_{f-2}
//   C1A = ((2f-1)/f) * s_f/s_{f-1},  C2A = ((f-1)/f) * s_f/s_{f-2}
// (s ratios are exact powers of 2 -> folding is bit-exact vs unscaled path)
__device__ __constant__ float C1A[7] = {
    3.f/2.f, 5.f/3.f, 7.f/4.f,
    (9.f/5.f)  * 0.25f,
    (11.f/6.f) * 0.125f,
    (13.f/7.f) * 0.0625f,
    (15.f/8.f) * 0.125f
};
__device__ __constant__ float C2A[7] = {
    1.f/2.f, 2.f/3.f, 3.f/4.f,
    (4.f/5.f) * 0.25f,
    (5.f/6.f) * 0.03125f,
    (6.f/7.f) * 7.8125e-3f,
    (7.f/8.f) * 7.8125e-3f
};

// ---------------------------------------------------------------- helpers ---
__device__ __forceinline__ uint32_t smem_u32(const void* p) {
    return (uint32_t)__cvta_generic_to_shared(p);
}
__device__ __forceinline__ void cp_async16(uint32_t dst, const void* src) {
    asm volatile("cp.async.cg.shared.global [%0], [%1], 16;"
                 :: "r"(dst), "l"(__cvta_generic_to_global(src)));
}
__device__ __forceinline__ void cp_commit() { asm volatile("cp.async.commit_group;"); }
__device__ __forceinline__ void cp_wait0() {
    asm volatile("cp.async.wait_group 0;" ::: "memory");
}
__device__ __forceinline__ void ldsm_x4(uint32_t* r, uint32_t addr) {
    asm volatile("ldmatrix.sync.aligned.m8n8.x4.shared.b16 {%0,%1,%2,%3}, [%4];"
                 : "=r"(r[0]), "=r"(r[1]), "=r"(r[2]), "=r"(r[3]) : "r"(addr));
}
__device__ __forceinline__ void ldsm_x4_t(uint32_t* r, uint32_t addr) {
    asm volatile("ldmatrix.sync.aligned.m8n8.x4.trans.shared.b16 {%0,%1,%2,%3}, [%4];"
                 : "=r"(r[0]), "=r"(r[1]), "=r"(r[2]), "=r"(r[3]) : "r"(addr));
}
__device__ __forceinline__ void mma16816f16(float* c, const uint32_t* a,
                                            uint32_t b0, uint32_t b1) {
    asm volatile(
        "mma.sync.aligned.m16n8k16.row.col.f32.f16.f16.f32 "
        "{%0,%1,%2,%3}, {%4,%5,%6,%7}, {%8,%9}, {%0,%1,%2,%3};"
        : "+f"(c[0]), "+f"(c[1]), "+f"(c[2]), "+f"(c[3])
        : "r"(a[0]), "r"(a[1]), "r"(a[2]), "r"(a[3]), "r"(b0), "r"(b1));
}
__device__ __forceinline__ uint32_t pack_h2(float a0, float a1) {
    uint32_t d;
    asm("cvt.rn.f16x2.f32 %0, %1, %2;" : "=r"(d) : "f"(a1), "f"(a0));
    return d;
}
__device__ __forceinline__ float clamp16(float v) {
    return fminf(fmaxf(v, -65000.f), 65000.f);
}

// ---------------------------------------------------------------- prepass ---
// g_B word index = ((c*32 + k)*512 + n) / 2,  c = ib*8 + (f-1).
// 2 groups (16 n-values) per thread -> 4 independent float4 loads (MLP 4).
__global__ void leg_prep_kernel(const float* __restrict__ w) {
    uint32_t g0 = (blockIdx.x * 256 + threadIdx.x) * 2;    // 262144 groups total
    #pragma unroll
    for (int gg = 0; gg < 2; ++gg) {
        uint32_t g  = g0 + gg;
        uint32_t n8 = g & 63;
        uint32_t q  = g >> 6;
        uint32_t k  = q & 31;
        uint32_t c  = q >> 5;
        uint32_t f  = (c & 7) + 1;
        uint32_t ib = c >> 3;
        const float sw = SCALE_W[f - 1];
        const float4* src = (const float4*)(w
            + ((size_t)(f * 512 + ib * 32 + k)) * 512 + n8 * 8);
        float4 v0 = src[0], v1 = src[1];
        uint4 o;
        o.x = pack_h2(v0.x * sw, v0.y * sw);
        o.y = pack_h2(v0.z * sw, v0.w * sw);
        o.z = pack_h2(v1.x * sw, v1.y * sw);
        o.w = pack_h2(v1.z * sw, v1.w * sw);
        *(uint4*)(g_B + (size_t)g * 4) = o;
    }
}

// bias2[o] = bias[o] + sum_i W[0,i,o].  Block per column, tree reduction.
__global__ void leg_bias_kernel(const float* __restrict__ w,
                                const float* __restrict__ bias) {
    __shared__ float red[128];
    const int o   = blockIdx.x;           // 512 blocks
    const int tid = threadIdx.x;          // 128 threads
    float s = 0.0f;
    #pragma unroll
    for (int j = 0; j < 4; ++j)
        s += w[(size_t)(tid + j * 128) * 512 + o];
    red[tid] = s;
    __syncthreads();
    #pragma unroll
    for (int off = 64; off > 0; off >>= 1) {
        if (tid < off) red[tid] += red[tid + off];
        __syncthreads();
    }
    if (tid == 0) g_bias2[o] = red[0] + bias[o];
}

// ------------------------------------------------------------ main kernel ---
__global__ __launch_bounds__(NTHR, 1)
void leg_mma_kernel(const float* __restrict__ x,
                    float* __restrict__ out)
{
    extern __shared__ char sm[];
    const uint32_t sb = smem_u32(sm);
    const int tid    = threadIdx.x;
    const int lane   = tid & 31;
    const int wid    = tid >> 5;
    const int warp_m = wid & 3;
    const int warp_n = wid >> 2;
    const int bn = blockIdx.x * BN;
    const int bm = blockIdx.y * BM;

    float acc[2][8][4];
    #pragma unroll
    for (int a = 0; a < 2; ++a)
        #pragma unroll
        for (int b = 0; b < 8; ++b)
            #pragma unroll
            for (int d = 0; d < 4; ++d) acc[a][b][d] = 0.0f;

    const int am  = tid >> 2;
    const int ai0 = (tid & 3) * 8;
    float xv[8], pm1[8], pm2[8];   // pm1/pm2 carry SCALED q values

    const uint32_t aRow = (uint32_t)(warp_m * 32 + (lane & 15)) * APITCH
                        + (uint32_t)(lane >> 4) * 16;
    const uint32_t bRow = (uint32_t)(lane & 15) * BPITCH
                        + ((uint32_t)(warp_n * 64) + (uint32_t)(lane >> 4) * 8) * 2;

    // ---- B stage loader: 4 chunks = 64KB (8 x 16B per thread)
    auto issue_load = [&](int t) {
        const int buf = t & 1;
        #pragma unroll
        for (int j = 0; j < 8; ++j) {
            int seg = tid + j * NTHR;      // 0..4095
            int d   = seg >> 10;           // 0..3
            int r   = seg & 1023;
            int k   = r >> 5;
            int n16 = r & 31;
            int c   = t * DPS + d;
            uint32_t dst = sb + SM_B + (uint32_t)(buf * DPS + d) * BTILE
                         + (uint32_t)k * BPITCH + (uint32_t)n16 * 16;
            const char* src = (const char*)g_B
                + (((size_t)c * 32 + k) * 512 + bn + n16 * 8) * 2;
            cp_async16(dst, src);
        }
        cp_commit();
    };

    issue_load(0);

    for (int t = 0; t < NSTG; ++t) {
        const int buf = t & 1;

        // ---- compute A (scaled q values) for the 4 chunks of stage t.
        #pragma unroll
        for (int d = 0; d < DPS; ++d) {
            const int c  = t * DPS + d;
            const int f  = (c & 7) + 1;    // 1..8
            float p[8];
            if (f == 1) {
                const int ib = c >> 3;
                const float4* xp = (const float4*)(x + (size_t)(bm + am) * 512
                                                   + ib * 32 + ai0);
                float4 v0 = xp[0], v1 = xp[1];
                xv[0]=v0.x; xv[1]=v0.y; xv[2]=v0.z; xv[3]=v0.w;
                xv[4]=v1.x; xv[5]=v1.y; xv[6]=v1.z; xv[7]=v1.w;
                #pragma unroll
                for (int j = 0; j < 8; ++j) { p[j] = xv[j]; pm2[j] = 1.0f; pm1[j] = xv[j]; }
            } else {
                const float c1 = C1A[f - 2];
                const float c2 = C2A[f - 2];
                #pragma unroll
                for (int j = 0; j < 8; ++j) {
                    float pn = c1 * xv[j] * pm1[j] - c2 * pm2[j];
                    pm2[j] = pm1[j]; pm1[j] = pn; p[j] = pn;
                }
            }
            // values are already scaled; clamp only where overflow is possible
            uint32_t wds[4];
            if (f >= 5) {
                #pragma unroll
                for (int j2 = 0; j2 < 4; ++j2)
                    wds[j2] = pack_h2(clamp16(p[2*j2]), clamp16(p[2*j2+1]));
            } else {
                #pragma unroll
                for (int j2 = 0; j2 < 4; ++j2)
                    wds[j2] = pack_h2(p[2*j2], p[2*j2+1]);
            }
            uint32_t aaddr = sb + SM_A + (uint32_t)(buf * DPS + d) * ATILE
                           + (uint32_t)am * APITCH + (uint32_t)ai0 * 2;
            asm volatile("st.shared.v4.b32 [%0], {%1,%2,%3,%4};"
                         :: "r"(aaddr), "r"(wds[0]), "r"(wds[1]), "r"(wds[2]), "r"(wds[3]));
        }

        cp_wait0();
        __syncthreads();                 // publish A(t)+B(t); retire MMA(t-1)
        if (t + 1 < NSTG) issue_load(t + 1);

        // ---- single-pass MMA over the 4 chunks (fine-grained ldsm)
        #pragma unroll
        for (int d = 0; d < DPS; ++d) {
            const uint32_t aT = sb + SM_A + (uint32_t)(buf * DPS + d) * ATILE + aRow;
            const uint32_t bT = sb + SM_B + (uint32_t)(buf * DPS + d) * BTILE + bRow;

            #pragma unroll
            for (int k16 = 0; k16 < 2; ++k16) {
                const uint32_t aOff = (uint32_t)k16 * 32;
                const uint32_t bOff = (uint32_t)(k16 * 16) * BPITCH;
                uint32_t ah[2][4], bb[4][4];

                ldsm_x4(ah[0], aT + aOff);
                ldsm_x4(ah[1], aT + aOff + 16 * APITCH);
                #pragma unroll
                for (int nf = 0; nf < 4; ++nf) ldsm_x4_t(bb[nf], bT + bOff + nf * 32);

                #pragma unroll
                for (int mf = 0; mf < 2; ++mf)
                    #pragma unroll
                    for (int nf = 0; nf < 4; ++nf) {
                        mma16816f16(acc[mf][nf * 2 + 0], ah[mf], bb[nf][0], bb[nf][1]);
                        mma16816f16(acc[mf][nf * 2 + 1], ah[mf], bb[nf][2], bb[nf][3]);
                    }
            }
        }
    }

    // ---- epilogue: bias add + store
    const int r0 = bm + warp_m * 32 + (lane >> 2);
    const int c0 = bn + warp_n * 64 + (lane & 3) * 2;
    #pragma unroll
    for (int mf = 0; mf < 2; ++mf) {
        #pragma unroll
        for (int nf = 0; nf < 8; ++nf) {
            const int row = r0 + mf * 16;
            const int col = c0 + nf * 8;
            const float2 bv = *(const float2*)(g_bias2 + col);
            float2 v0, v1;
            v0.x = acc[mf][nf][0] + bv.x;  v0.y = acc[mf][nf][1] + bv.y;
            v1.x = acc[mf][nf][2] + bv.x;  v1.y = acc[mf][nf][3] + bv.y;
            *(float2*)(out + (size_t)row * 512 + col)       = v0;
            *(float2*)(out + (size_t)(row + 8) * 512 + col) = v1;
        }
    }
}

// ------------------------------------------------------------------ launch --
extern "C" void kernel_launch(void* const* d_in, const int* in_sizes, int n_in,
                              void* d_out, int out_size)
{
    const float* x    = (const float*)d_in[0];
    const float* w    = (const float*)d_in[1];
    const float* bias = (const float*)d_in[2];
    float* out        = (float*)d_out;

    const int B = in_sizes[0] / 512;             // 16384

    cudaFuncSetAttribute(leg_mma_kernel,
                         cudaFuncAttributeMaxDynamicSharedMemorySize,
                         SMEM_TOTAL);

    leg_prep_kernel<<<512, 256>>>(w);            // 262144 groups, 2 per thread
    leg_bias_kernel<<<512, 128>>>(w, bias);      // block-per-column reduction

    dim3 grid(512 / BN, B / BM);                 // (2, 128)
    leg_mma_kernel<<<grid, NTHR, SMEM_TOTAL>>>(x, out);
}